// round 14
// baseline (speedup 1.0000x reference)
#include <cuda_runtime.h>
#include <math.h>

#define BB 128
#define II 512
#define NN 512
#define WD 32
#define RR 4
#define EPSV 1e-6f

// output element offsets (concat order: rv, mem, link, prec, rw, ww, usage)
#define O_RV   0
#define O_MEM  16384
#define O_LINK 2113536
#define O_PREC 35667968
#define O_RW   35733504
#define O_WW   35995648
#define O_US   36061184

#define NSTRIP 8   // strips per batch in k_link (64 rows each)

// scratch (device globals; no allocation allowed)
__device__ float g_ifc[BB][256];               // activated interface vectors (rm raw)
__device__ float g_fw[BB * RR * NN];           // forward read weights (full)
__device__ float g_bwp[BB * NSTRIP * RR * NN]; // backward partials, per strip
__device__ float g_mnorm[BB * NN];             // ||memory_new row||

struct HeadPtrs { const float* W[10]; const float* Bv[10]; };

// ---------------------------------------------------------------- reductions
__device__ __forceinline__ float warpRedAdd(float v) {
    #pragma unroll
    for (int o = 16; o; o >>= 1) v += __shfl_xor_sync(0xffffffffu, v, o);
    return v;
}

__device__ __forceinline__ float blockRedMax(float v, float* red) {
    #pragma unroll
    for (int o = 16; o; o >>= 1) v = fmaxf(v, __shfl_xor_sync(0xffffffffu, v, o));
    int w = threadIdx.x >> 5, l = threadIdx.x & 31;
    if (l == 0) red[w] = v;
    __syncthreads();
    if (threadIdx.x < 32) {
        float x = (l < 16) ? red[l] : -INFINITY;
        #pragma unroll
        for (int o = 8; o; o >>= 1) x = fmaxf(x, __shfl_xor_sync(0xffffffffu, x, o));
        if (l == 0) red[16] = x;
    }
    __syncthreads();
    float r = red[16];
    __syncthreads();
    return r;
}

__device__ __forceinline__ float blockRedSum(float v, float* red) {
    v = warpRedAdd(v);
    int w = threadIdx.x >> 5, l = threadIdx.x & 31;
    if (l == 0) red[w] = v;
    __syncthreads();
    if (threadIdx.x < 32) {
        float x = (l < 16) ? red[l] : 0.f;
        #pragma unroll
        for (int o = 8; o; o >>= 1) x += __shfl_xor_sync(0xffffffffu, x, o);
        if (l == 0) red[16] = x;
    }
    __syncthreads();
    float r = red[16];
    __syncthreads();
    return r;
}

// Reduce 8 independent per-lane values across the warp with 9 SHFL total.
__device__ __forceinline__ float multiRed8(float* v, int lane) {
    bool up = (lane & 16);
    #pragma unroll
    for (int k = 0; k < 4; k++) {
        float send = up ? v[k] : v[k + 4];
        float recv = __shfl_xor_sync(0xffffffffu, send, 16);
        v[k] = (up ? v[k + 4] : v[k]) + recv;
    }
    up = (lane & 8);
    #pragma unroll
    for (int k = 0; k < 2; k++) {
        float send = up ? v[k] : v[k + 2];
        float recv = __shfl_xor_sync(0xffffffffu, send, 8);
        v[k] = (up ? v[k + 2] : v[k]) + recv;
    }
    up = (lane & 4);
    {
        float send = up ? v[0] : v[1];
        float recv = __shfl_xor_sync(0xffffffffu, send, 4);
        v[0] = (up ? v[1] : v[0]) + recv;
    }
    v[0] += __shfl_xor_sync(0xffffffffu, v[0], 2);
    v[0] += __shfl_xor_sync(0xffffffffu, v[0], 1);
    return v[0];
}

// --------------------------------------------------------------- K1: linears
// dims flat layout: rk 0-127 | rs 128-131 | wk 132-163 | ws 164 | ev 165-196
//                   wv 197-228 | fg 229-232 | ag 233 | wg 234 | rm 235-246
__device__ __forceinline__ float sp_act(float x) {
    return fmaxf(x, 0.f) + log1pf(expf(-fabsf(x)));
}
__device__ __forceinline__ float actfn(int j, float x) {
    if (j < 128) return tanhf(x);
    if (j < 132) return sp_act(x);
    if (j < 164) return tanhf(x);
    if (j == 164) return sp_act(x);
    if (j < 197) return 1.f / (1.f + expf(-x));     // ev sigmoid
    if (j < 229) return tanhf(x);                   // wv
    if (j < 235) return 1.f / (1.f + expf(-x));     // fg, ag, wg
    return x;                                       // rm raw (softmax later)
}

__global__ void __launch_bounds__(256) k_interface(const float* __restrict__ xi, HeadPtrs P) {
    __shared__ float xi_s[8][II];   // 16 KB
    int t = threadIdx.x;
    int bb0 = blockIdx.y * 8;
    for (int idx = t; idx < 8 * II; idx += 256)
        xi_s[idx >> 9][idx & 511] = xi[(size_t)(bb0 + (idx >> 9)) * II + (idx & 511)];
    __syncthreads();

    int wid = t >> 5, lane = t & 31;
    int j = blockIdx.x * 8 + wid;
    if (j >= 247) return;

    int h, off;
    if (j < 128)      { h = 0; off = j; }
    else if (j < 132) { h = 1; off = j - 128; }
    else if (j < 164) { h = 2; off = j - 132; }
    else if (j < 165) { h = 3; off = j - 164; }
    else if (j < 197) { h = 4; off = j - 165; }
    else if (j < 229) { h = 5; off = j - 197; }
    else if (j < 233) { h = 6; off = j - 229; }
    else if (j < 234) { h = 7; off = j - 233; }
    else if (j < 235) { h = 8; off = j - 234; }
    else              { h = 9; off = j - 235; }
    const float* wrow = P.W[h] + (size_t)off * II;
    float bias = P.Bv[h][off];

    float wreg[16];
    #pragma unroll
    for (int k = 0; k < 16; k++) wreg[k] = wrow[lane + 32 * k];

    for (int bb = 0; bb < 8; bb++) {
        float acc = 0.f;
        #pragma unroll
        for (int k = 0; k < 16; k++) acc = fmaf(wreg[k], xi_s[bb][lane + 32 * k], acc);
        acc = warpRedAdd(acc);
        if (lane == 0) g_ifc[bb0 + bb][j] = actfn(j, acc + bias);
    }
}

// ------------------- K2: per-batch usage/sort/ww/prec + fused memory write
// Memory row + precedence loaded at kernel start; their latency hides behind
// the bitonic sort. Intra-warp sort stages register-resident via shfl.
__global__ void __launch_bounds__(512) k_batch(
    const float* __restrict__ mem_in, const float* __restrict__ prec_in,
    const float* __restrict__ rw_in, const float* __restrict__ wwp_in,
    const float* __restrict__ usage_in,
    float* __restrict__ o_ww, float* __restrict__ o_prec, float* __restrict__ o_us,
    float* __restrict__ o_mem)
{
    __shared__ float sk[NN];
    __shared__ int   si[NN];
    __shared__ float alloc_s[NN];
    __shared__ float wk_s[WD], er_s[WD], wv_s[WD];
    __shared__ float red[17];
    __shared__ float wprod[17];

    int b = blockIdx.x, t = threadIdx.x;
    int lane = t & 31, wid = t >> 5;
    const float* ifcb = g_ifc[b];

    // ---- early loads: memory row + precedence (latency hidden by sort) ----
    float4 mreg[8];
    const float4* mrp = (const float4*)(mem_in + ((size_t)(b * NN + t)) * WD);
    #pragma unroll
    for (int q = 0; q < 8; q++) mreg[q] = mrp[q];
    float prec_v = prec_in[b * NN + t];

    // usage update (retention psi)
    float psi = 1.f;
    #pragma unroll
    for (int r = 0; r < RR; r++) {
        float fr = ifcb[229 + r];
        psi *= (1.f - fr * rw_in[((size_t)(b * RR + r)) * NN + t]);
    }
    float u = usage_in[b * NN + t], wp = wwp_in[b * NN + t];
    float un = (u + wp - u * wp) * psi;
    o_us[b * NN + t] = un;
    if (t < WD) {
        wk_s[t] = ifcb[132 + t];
        er_s[t] = ifcb[165 + t];
        wv_s[t] = ifcb[197 + t];
    }

    // ---- bitonic sort ascending (key + original index) ----
    // phase A: k = 2..32 entirely intra-warp, register resident
    {
        float a = un;
        int ia = t;
        #pragma unroll
        for (int k = 2; k <= 32; k <<= 1) {
            #pragma unroll
            for (int j = k >> 1; j >= 1; j >>= 1) {
                float pk = __shfl_xor_sync(0xffffffffu, a, j);
                int   pi = __shfl_xor_sync(0xffffffffu, ia, j);
                bool up = ((t & k) == 0);
                bool lower = ((t & j) == 0);
                bool keepmin = (lower == up);
                bool take = keepmin ? (pk < a) : (pk > a);
                if (take) { a = pk; ia = pi; }
            }
        }
        sk[t] = a; si[t] = ia;
    }
    __syncthreads();

    // phase B: k = 64..512 ; shared stages for j>=32, warp tail for j<=16
    for (int k = 64; k <= NN; k <<= 1) {
        for (int j = k >> 1; j >= 32; j >>= 1) {
            int ixj = t ^ j;
            if (ixj > t) {
                float a = sk[t], c = sk[ixj];
                bool up = ((t & k) == 0);
                if (up ? (a > c) : (a < c)) {
                    sk[t] = c; sk[ixj] = a;
                    int tmp = si[t]; si[t] = si[ixj]; si[ixj] = tmp;
                }
            }
            __syncthreads();
        }
        {
            float a = sk[t]; int ia = si[t];
            bool up = ((t & k) == 0);
            #pragma unroll
            for (int j = 16; j >= 1; j >>= 1) {
                float pk = __shfl_xor_sync(0xffffffffu, a, j);
                int   pi = __shfl_xor_sync(0xffffffffu, ia, j);
                bool lower = ((t & j) == 0);
                bool keepmin = (lower == up);
                bool take = keepmin ? (pk < a) : (pk > a);
                if (take) { a = pk; ia = pi; }
            }
            sk[t] = a; si[t] = ia;
        }
        __syncthreads();
    }

    // ---- exclusive cumprod of sorted usage via warp scan ----
    float key = sk[t];
    float xs = key;
    #pragma unroll
    for (int o = 1; o < 32; o <<= 1) {
        float y = __shfl_up_sync(0xffffffffu, xs, o);
        if (lane >= o) xs *= y;
    }
    if (lane == 31) wprod[wid] = xs;
    __syncthreads();
    if (t < 32) {
        float p = (t < 16) ? wprod[t] : 1.f;
        #pragma unroll
        for (int o = 1; o < 16; o <<= 1) {
            float y = __shfl_up_sync(0xffffffffu, p, o);
            if (lane >= o) p *= y;
        }
        if (t < 16) wprod[t] = p;
    }
    __syncthreads();
    float pre = (wid == 0) ? 1.f : wprod[wid - 1];
    float exclw = __shfl_up_sync(0xffffffffu, xs, 1);
    float excl = (lane == 0) ? pre : (exclw * pre);
    alloc_s[si[t]] = (1.f - key) * excl;   // scatter (permutation)

    // write content addressing on OLD memory (row already in registers)
    float kn2 = 0.f;
    #pragma unroll
    for (int w = 0; w < WD; w++) kn2 += wk_s[w] * wk_s[w];
    float knorm = sqrtf(kn2);

    const float4* wk4 = (const float4*)wk_s;
    float dot = 0.f, n2 = 0.f;
    #pragma unroll
    for (int q = 0; q < 8; q++) {
        float4 m = mreg[q], k4 = wk4[q];
        dot += m.x * k4.x + m.y * k4.y + m.z * k4.z + m.w * k4.w;
        n2  += m.x * m.x + m.y * m.y + m.z * m.z + m.w * m.w;
    }
    float wstr = ifcb[164];
    float s = wstr * dot / (sqrtf(n2) * knorm + EPSV);
    float mx = blockRedMax(s, red);          // syncthreads inside also fences alloc_s
    float e = expf(s - mx);
    float sum = blockRedSum(e, red);
    float wc = e / sum;

    float ag = ifcb[233], wg = ifcb[234];
    float av = alloc_s[t];
    float wwv = wg * (ag * av + (1.f - ag) * wc);
    o_ww[b * NN + t] = wwv;
    float sww = blockRedSum(wwv, red);
    o_prec[b * NN + t] = (1.f - sww) * prec_v + wwv;

    // fused memory write + row norm (this thread owns row t, data in mreg)
    const float4* er4 = (const float4*)er_s;
    const float4* wv4 = (const float4*)wv_s;
    float4* mo = (float4*)(o_mem + ((size_t)(b * NN + t)) * WD);
    float nrm2 = 0.f;
    #pragma unroll
    for (int q = 0; q < 8; q++) {
        float4 m = mreg[q], ee = er4[q], vv = wv4[q], o;
        o.x = m.x * (1.f - wwv * ee.x) + wwv * vv.x;
        o.y = m.y * (1.f - wwv * ee.y) + wwv * vv.y;
        o.z = m.z * (1.f - wwv * ee.z) + wwv * vv.z;
        o.w = m.w * (1.f - wwv * ee.w) + wwv * vv.w;
        mo[q] = o;
        nrm2 += o.x * o.x + o.y * o.y + o.z * o.z + o.w * o.w;
    }
    g_mnorm[b * NN + t] = sqrtf(nrm2);
}

// -------------------------------------------- K4: link update + fused fw / bw
// 3-buffer software pipeline: chunk c+2 loads issue while chunk c computes,
// doubling the DRAM-latency coverage vs the 2-buffer version.
__global__ void __launch_bounds__(256, 3) k_link(
    const float* __restrict__ link_in, const float* __restrict__ prec_in,
    const float* __restrict__ rw_in, const float* __restrict__ ww,
    float* __restrict__ o_link)
{
    __shared__ float4 rw4_s[NN];       // 8 KB
    __shared__ float  ww_s[NN];        // 2 KB
    __shared__ float  fw_s[RR][68];    // ~1 KB (padded)
    __shared__ float  bw_s[RR][NN];    // 8 KB

    int b = blockIdx.y, strip = blockIdx.x;   // strip 0..7, 64 rows each
    int t = threadIdx.x;
    int grp = t >> 7;                          // 0..1
    int tig = t & 127;
    int lane = t & 31;

    for (int i = t; i < NN; i += 256) {
        float4 v;
        v.x = rw_in[((size_t)(b * RR + 0)) * NN + i];
        v.y = rw_in[((size_t)(b * RR + 1)) * NN + i];
        v.z = rw_in[((size_t)(b * RR + 2)) * NN + i];
        v.w = rw_in[((size_t)(b * RR + 3)) * NN + i];
        rw4_s[i] = v;
        ww_s[i] = ww[b * NN + i];
    }
    for (int i = t; i < RR * 68; i += 256) (&fw_s[0][0])[i] = 0.f;
    for (int i = t; i < RR * NN; i += 256) (&bw_s[0][0])[i] = 0.f;
    __syncthreads();

    int m0 = tig * 4;
    float4 prec_own = *(const float4*)(prec_in + (size_t)b * NN + m0);
    float4 rw_own0 = rw4_s[m0 + 0];
    float4 rw_own1 = rw4_s[m0 + 1];
    float4 rw_own2 = rw4_s[m0 + 2];
    float4 rw_own3 = rw4_s[m0 + 3];
    float ww0 = ww_s[m0 + 0], ww1 = ww_s[m0 + 1];
    float ww2 = ww_s[m0 + 2], ww3 = ww_s[m0 + 3];

    int row0 = strip * 64 + grp * 32;
    const float* Lp = link_in + ((size_t)b * NN + row0) * NN + m0;
    float* Op = o_link + ((size_t)b * NN + row0) * NN + m0;

    float bacc[16];
    #pragma unroll
    for (int k = 0; k < 16; k++) bacc[k] = 0.f;

    // 16 chunks of 2 rows; 3-buffer pipeline (prefetch 2 chunks ahead)
    float4 A0 = __ldcs((const float4*)(Lp + 0 * NN));
    float4 A1 = __ldcs((const float4*)(Lp + 1 * NN));
    float4 B0 = __ldcs((const float4*)(Lp + 2 * NN));
    float4 B1 = __ldcs((const float4*)(Lp + 3 * NN));

    for (int c = 0; c < 16; c++) {
        float4 C0, C1;
        if (c < 14) {
            C0 = __ldcs((const float4*)(Lp + (size_t)(2 * c + 4) * NN));
            C1 = __ldcs((const float4*)(Lp + (size_t)(2 * c + 5) * NN));
        }

        float vals[8];
        #pragma unroll
        for (int j = 0; j < 2; j++) {
            float4 L4 = (j == 0) ? A0 : A1;
            int n = row0 + 2 * c + j;
            float wwn = ww_s[n];
            float4 rwn = rw4_s[n];
            float cn = 1.f - wwn;
            float l0 = fmaf(cn - ww0, L4.x, wwn * prec_own.x);
            float l1 = fmaf(cn - ww1, L4.y, wwn * prec_own.y);
            float l2 = fmaf(cn - ww2, L4.z, wwn * prec_own.z);
            float l3 = fmaf(cn - ww3, L4.w, wwn * prec_own.w);
            l0 = (n == m0 + 0) ? 0.f : l0;
            l1 = (n == m0 + 1) ? 0.f : l1;
            l2 = (n == m0 + 2) ? 0.f : l2;
            l3 = (n == m0 + 3) ? 0.f : l3;
            __stcs((float4*)(Op + (size_t)(2 * c + j) * NN), make_float4(l0, l1, l2, l3));

            vals[j * 4 + 0] = l0 * rw_own0.x + l1 * rw_own1.x + l2 * rw_own2.x + l3 * rw_own3.x;
            vals[j * 4 + 1] = l0 * rw_own0.y + l1 * rw_own1.y + l2 * rw_own2.y + l3 * rw_own3.y;
            vals[j * 4 + 2] = l0 * rw_own0.z + l1 * rw_own1.z + l2 * rw_own2.z + l3 * rw_own3.z;
            vals[j * 4 + 3] = l0 * rw_own0.w + l1 * rw_own1.w + l2 * rw_own2.w + l3 * rw_own3.w;

            bacc[0]  = fmaf(l0, rwn.x, bacc[0]);  bacc[1]  = fmaf(l0, rwn.y, bacc[1]);
            bacc[2]  = fmaf(l0, rwn.z, bacc[2]);  bacc[3]  = fmaf(l0, rwn.w, bacc[3]);
            bacc[4]  = fmaf(l1, rwn.x, bacc[4]);  bacc[5]  = fmaf(l1, rwn.y, bacc[5]);
            bacc[6]  = fmaf(l1, rwn.z, bacc[6]);  bacc[7]  = fmaf(l1, rwn.w, bacc[7]);
            bacc[8]  = fmaf(l2, rwn.x, bacc[8]);  bacc[9]  = fmaf(l2, rwn.y, bacc[9]);
            bacc[10] = fmaf(l2, rwn.z, bacc[10]); bacc[11] = fmaf(l2, rwn.w, bacc[11]);
            bacc[12] = fmaf(l3, rwn.x, bacc[12]); bacc[13] = fmaf(l3, rwn.y, bacc[13]);
            bacc[14] = fmaf(l3, rwn.z, bacc[14]); bacc[15] = fmaf(l3, rwn.w, bacc[15]);
        }

        // joint reduction of 8 values (2 rows x 4 r) in 9 SHFL
        float red8 = multiRed8(vals, lane);
        if ((lane & 3) == 0) {
            int v = (((lane >> 4) & 1) << 2) | (((lane >> 3) & 1) << 1) | ((lane >> 2) & 1);
            int jrow = v >> 2;          // 0..1
            int rr = v & 3;             // 0..3
            atomicAdd(&fw_s[rr][grp * 32 + 2 * c + jrow], red8);
        }

        A0 = B0; A1 = B1; B0 = C0; B1 = C1;
    }

    // flush bw column partials (2 groups collide per address -> 2-way atomics, once)
    #pragma unroll
    for (int j = 0; j < 4; j++) {
        atomicAdd(&bw_s[0][m0 + j], bacc[j * 4 + 0]);
        atomicAdd(&bw_s[1][m0 + j], bacc[j * 4 + 1]);
        atomicAdd(&bw_s[2][m0 + j], bacc[j * 4 + 2]);
        atomicAdd(&bw_s[3][m0 + j], bacc[j * 4 + 3]);
    }
    __syncthreads();

    for (int i = t; i < RR * 64; i += 256) {
        int r = i >> 6, nl = i & 63;
        g_fw[((size_t)(b * RR + r)) * NN + strip * 64 + nl] = fw_s[r][nl];
    }
    for (int i = t; i < RR * NN; i += 256)
        g_bwp[((size_t)b * NSTRIP + strip) * (RR * NN) + i] = (&bw_s[0][0])[i];
}

// ---------------------- K5: read content softmax (joint 4-head), combine, rv
// bw/fw combine inputs load BEFORE the softmax barriers so their DRAM latency
// overlaps the reductions.
__global__ void __launch_bounds__(512) k_read(
    const float* __restrict__ o_mem, float* __restrict__ o_rw, float* __restrict__ o_rv)
{
    __shared__ float rk_s[RR][WD];
    __shared__ float rc_s[RR][NN];
    __shared__ float red4[RR][16];
    __shared__ float gmax[RR], gsum[RR];
    __shared__ float knorm_s[RR], rs_s[RR], modes_s[RR][3];
    __shared__ float rv_part[4][RR * WD];

    int b = blockIdx.x, t = threadIdx.x;
    int lane = t & 31, wid = t >> 5;
    const float* ifcb = g_ifc[b];
    if (t < 128) rk_s[t >> 5][t & 31] = ifcb[t];
    if (t >= 128 && t < 132) rs_s[t - 128] = ifcb[t];
    __syncthreads();
    if (t < RR) {
        float s2 = 0.f;
        #pragma unroll
        for (int w = 0; w < WD; w++) s2 += rk_s[t][w] * rk_s[t][w];
        knorm_s[t] = sqrtf(s2);
    }
    if (t >= 8 && t < 8 + RR) {
        int r = t - 8;
        float a = ifcb[235 + r * 3], c = ifcb[236 + r * 3], d = ifcb[237 + r * 3];
        float mx = fmaxf(a, fmaxf(c, d));
        float ea = expf(a - mx), ec = expf(c - mx), ed = expf(d - mx);
        float inv = 1.f / (ea + ec + ed);
        modes_s[r][0] = ea * inv; modes_s[r][1] = ec * inv; modes_s[r][2] = ed * inv;
    }
    __syncthreads();

    // this thread's updated-memory row in registers
    float4 mreg[8];
    const float4* mr = (const float4*)(o_mem + ((size_t)(b * NN + t)) * WD);
    #pragma unroll
    for (int q = 0; q < 8; q++) mreg[q] = mr[q];
    float nm = g_mnorm[b * NN + t];

    // all 4 head scores for this row
    float sval[RR];
    #pragma unroll
    for (int r = 0; r < RR; r++) {
        const float4* rk4 = (const float4*)rk_s[r];
        float dot = 0.f;
        #pragma unroll
        for (int q = 0; q < 8; q++) {
            float4 k4 = rk4[q];
            dot += mreg[q].x * k4.x + mreg[q].y * k4.y + mreg[q].z * k4.z + mreg[q].w * k4.w;
        }
        sval[r] = rs_s[r] * dot / (nm * knorm_s[r] + EPSV);
    }

    // EARLY-ISSUE combine inputs: 36 independent loads overlap the barriers below
    float bwv[RR], fwv[RR];
    #pragma unroll
    for (int r = 0; r < RR; r++) {
        float acc = 0.f;
        #pragma unroll
        for (int s = 0; s < NSTRIP; s++)
            acc += g_bwp[((size_t)b * NSTRIP + s) * (RR * NN) + r * NN + t];
        bwv[r] = acc;
        fwv[r] = g_fw[((size_t)(b * RR + r)) * NN + t];
    }

    // joint block max for 4 heads (2 barriers)
    #pragma unroll
    for (int r = 0; r < RR; r++) {
        float v = sval[r];
        #pragma unroll
        for (int o = 16; o; o >>= 1) v = fmaxf(v, __shfl_xor_sync(0xffffffffu, v, o));
        if (lane == 0) red4[r][wid] = v;
    }
    __syncthreads();
    if (wid < RR) {
        float x = (lane < 16) ? red4[wid][lane] : -INFINITY;
        #pragma unroll
        for (int o = 16; o; o >>= 1) x = fmaxf(x, __shfl_xor_sync(0xffffffffu, x, o));
        if (lane == 0) gmax[wid] = x;
    }
    __syncthreads();

    // joint block sum for 4 heads (2 barriers)
    float ex[RR];
    #pragma unroll
    for (int r = 0; r < RR; r++) {
        ex[r] = expf(sval[r] - gmax[r]);
        float v = ex[r];
        #pragma unroll
        for (int o = 16; o; o >>= 1) v += __shfl_xor_sync(0xffffffffu, v, o);
        if (lane == 0) red4[r][wid] = v;
    }
    __syncthreads();
    if (wid < RR) {
        float x = (lane < 16) ? red4[wid][lane] : 0.f;
        #pragma unroll
        for (int o = 16; o; o >>= 1) x += __shfl_xor_sync(0xffffffffu, x, o);
        if (lane == 0) gsum[wid] = x;
    }
    __syncthreads();

    // combine modes: rw_new = m0*bw + m1*rc + m2*fw
    #pragma unroll
    for (int r = 0; r < RR; r++) {
        float rc = ex[r] / gsum[r];
        float val = modes_s[r][0] * bwv[r] + modes_s[r][1] * rc + modes_s[r][2] * fwv[r];
        o_rw[((size_t)(b * RR + r)) * NN + t] = val;
        rc_s[r][t] = val;
    }
    __syncthreads();

    // read vectors: rv[r][w] = sum_n rw[r][n] * mem[n][w]  (512 threads, 4 n-chunks)
    {
        int chunk = t >> 7;           // 0..3
        int p = t & 127;              // (r,w) pair
        int r = p >> 5, w = p & 31;
        float acc = 0.f;
        const float* mb = o_mem + (size_t)b * NN * WD;
        int n0 = chunk * 128;
        #pragma unroll 4
        for (int n = n0; n < n0 + 128; n++)
            acc = fmaf(rc_s[r][n], mb[(size_t)n * WD + w], acc);
        rv_part[chunk][p] = acc;
    }
    __syncthreads();
    if (t < RR * WD)
        o_rv[(size_t)b * RR * WD + t] =
            rv_part[0][t] + rv_part[1][t] + rv_part[2][t] + rv_part[3][t];
}

// ------------------------------------------------------------------ launcher
extern "C" void kernel_launch(void* const* d_in, const int* in_sizes, int n_in,
                              void* d_out, int out_size)
{
    (void)in_sizes; (void)n_in; (void)out_size;
    const float* xi       = (const float*)d_in[0];
    const float* mem_in   = (const float*)d_in[1];
    const float* link_in  = (const float*)d_in[2];
    const float* prec_in  = (const float*)d_in[3];
    const float* rw_in    = (const float*)d_in[4];
    const float* wwp_in   = (const float*)d_in[5];
    const float* usage_in = (const float*)d_in[6];

    HeadPtrs P;
    for (int h = 0; h < 10; h++) {
        P.W[h]  = (const float*)d_in[7 + 2 * h];
        P.Bv[h] = (const float*)d_in[8 + 2 * h];
    }

    float* out    = (float*)d_out;
    float* o_rv   = out + O_RV;
    float* o_mem  = out + O_MEM;
    float* o_link = out + O_LINK;
    float* o_prec = out + O_PREC;
    float* o_rw   = out + O_RW;
    float* o_ww   = out + O_WW;
    float* o_us   = out + O_US;

    k_interface<<<dim3(31, 16), 256>>>(xi, P);
    k_batch<<<BB, 512>>>(mem_in, prec_in, rw_in, wwp_in, usage_in, o_ww, o_prec, o_us, o_mem);
    k_link<<<dim3(NSTRIP, BB), 256>>>(link_in, prec_in, rw_in, o_ww, o_link);
    k_read<<<BB, 512>>>(o_mem, o_rw, o_rv);
}

// round 15
// speedup vs baseline: 1.0832x; 1.0832x over previous
#include <cuda_runtime.h>
#include <math.h>

#define BB 128
#define II 512
#define NN 512
#define WD 32
#define RR 4
#define EPSV 1e-6f

// output element offsets (concat order: rv, mem, link, prec, rw, ww, usage)
#define O_RV   0
#define O_MEM  16384
#define O_LINK 2113536
#define O_PREC 35667968
#define O_RW   35733504
#define O_WW   35995648
#define O_US   36061184

#define NSTRIP 8   // strips per batch in k_link (64 rows each)

// scratch (device globals; no allocation allowed)
__device__ float g_ifc[BB][256];               // activated interface vectors (rm raw)
__device__ float g_fw[BB * RR * NN];           // forward read weights (full)
__device__ float g_bwp[BB * NSTRIP * RR * NN]; // backward partials, per strip
__device__ float g_mnorm[BB * NN];             // ||memory_new row||

struct HeadPtrs { const float* W[10]; const float* Bv[10]; };

// ---------------------------------------------------------------- reductions
__device__ __forceinline__ float warpRedAdd(float v) {
    #pragma unroll
    for (int o = 16; o; o >>= 1) v += __shfl_xor_sync(0xffffffffu, v, o);
    return v;
}

__device__ __forceinline__ float blockRedMax(float v, float* red) {
    #pragma unroll
    for (int o = 16; o; o >>= 1) v = fmaxf(v, __shfl_xor_sync(0xffffffffu, v, o));
    int w = threadIdx.x >> 5, l = threadIdx.x & 31;
    if (l == 0) red[w] = v;
    __syncthreads();
    if (threadIdx.x < 32) {
        float x = (l < 16) ? red[l] : -INFINITY;
        #pragma unroll
        for (int o = 8; o; o >>= 1) x = fmaxf(x, __shfl_xor_sync(0xffffffffu, x, o));
        if (l == 0) red[16] = x;
    }
    __syncthreads();
    float r = red[16];
    __syncthreads();
    return r;
}

__device__ __forceinline__ float blockRedSum(float v, float* red) {
    v = warpRedAdd(v);
    int w = threadIdx.x >> 5, l = threadIdx.x & 31;
    if (l == 0) red[w] = v;
    __syncthreads();
    if (threadIdx.x < 32) {
        float x = (l < 16) ? red[l] : 0.f;
        #pragma unroll
        for (int o = 8; o; o >>= 1) x += __shfl_xor_sync(0xffffffffu, x, o);
        if (l == 0) red[16] = x;
    }
    __syncthreads();
    float r = red[16];
    __syncthreads();
    return r;
}

// Reduce 8 independent per-lane values across the warp with 9 SHFL total.
__device__ __forceinline__ float multiRed8(float* v, int lane) {
    bool up = (lane & 16);
    #pragma unroll
    for (int k = 0; k < 4; k++) {
        float send = up ? v[k] : v[k + 4];
        float recv = __shfl_xor_sync(0xffffffffu, send, 16);
        v[k] = (up ? v[k + 4] : v[k]) + recv;
    }
    up = (lane & 8);
    #pragma unroll
    for (int k = 0; k < 2; k++) {
        float send = up ? v[k] : v[k + 2];
        float recv = __shfl_xor_sync(0xffffffffu, send, 8);
        v[k] = (up ? v[k + 2] : v[k]) + recv;
    }
    up = (lane & 4);
    {
        float send = up ? v[0] : v[1];
        float recv = __shfl_xor_sync(0xffffffffu, send, 4);
        v[0] = (up ? v[1] : v[0]) + recv;
    }
    v[0] += __shfl_xor_sync(0xffffffffu, v[0], 2);
    v[0] += __shfl_xor_sync(0xffffffffu, v[0], 1);
    return v[0];
}

// --------------------------------------------------------------- K1: linears
// dims flat layout: rk 0-127 | rs 128-131 | wk 132-163 | ws 164 | ev 165-196
//                   wv 197-228 | fg 229-232 | ag 233 | wg 234 | rm 235-246
__device__ __forceinline__ float sp_act(float x) {
    return fmaxf(x, 0.f) + log1pf(expf(-fabsf(x)));
}
__device__ __forceinline__ float actfn(int j, float x) {
    if (j < 128) return tanhf(x);
    if (j < 132) return sp_act(x);
    if (j < 164) return tanhf(x);
    if (j == 164) return sp_act(x);
    if (j < 197) return 1.f / (1.f + expf(-x));     // ev sigmoid
    if (j < 229) return tanhf(x);                   // wv
    if (j < 235) return 1.f / (1.f + expf(-x));     // fg, ag, wg
    return x;                                       // rm raw (softmax later)
}

__global__ void __launch_bounds__(256) k_interface(const float* __restrict__ xi, HeadPtrs P) {
    __shared__ float xi_s[8][II];   // 16 KB
    int t = threadIdx.x;
    int bb0 = blockIdx.y * 8;
    for (int idx = t; idx < 8 * II; idx += 256)
        xi_s[idx >> 9][idx & 511] = xi[(size_t)(bb0 + (idx >> 9)) * II + (idx & 511)];
    __syncthreads();

    int wid = t >> 5, lane = t & 31;
    int j = blockIdx.x * 8 + wid;
    if (j >= 247) return;

    int h, off;
    if (j < 128)      { h = 0; off = j; }
    else if (j < 132) { h = 1; off = j - 128; }
    else if (j < 164) { h = 2; off = j - 132; }
    else if (j < 165) { h = 3; off = j - 164; }
    else if (j < 197) { h = 4; off = j - 165; }
    else if (j < 229) { h = 5; off = j - 197; }
    else if (j < 233) { h = 6; off = j - 229; }
    else if (j < 234) { h = 7; off = j - 233; }
    else if (j < 235) { h = 8; off = j - 234; }
    else              { h = 9; off = j - 235; }
    const float* wrow = P.W[h] + (size_t)off * II;
    float bias = P.Bv[h][off];

    float wreg[16];
    #pragma unroll
    for (int k = 0; k < 16; k++) wreg[k] = wrow[lane + 32 * k];

    for (int bb = 0; bb < 8; bb++) {
        float acc = 0.f;
        #pragma unroll
        for (int k = 0; k < 16; k++) acc = fmaf(wreg[k], xi_s[bb][lane + 32 * k], acc);
        acc = warpRedAdd(acc);
        if (lane == 0) g_ifc[bb0 + bb][j] = actfn(j, acc + bias);
    }
}

// ------------------- K2: per-batch usage/sort/ww/prec + fused memory write
// Memory row + precedence loaded at kernel start; their latency hides behind
// the bitonic sort. Intra-warp sort stages register-resident via shfl.
__global__ void __launch_bounds__(512) k_batch(
    const float* __restrict__ mem_in, const float* __restrict__ prec_in,
    const float* __restrict__ rw_in, const float* __restrict__ wwp_in,
    const float* __restrict__ usage_in,
    float* __restrict__ o_ww, float* __restrict__ o_prec, float* __restrict__ o_us,
    float* __restrict__ o_mem)
{
    __shared__ float sk[NN];
    __shared__ int   si[NN];
    __shared__ float alloc_s[NN];
    __shared__ float wk_s[WD], er_s[WD], wv_s[WD];
    __shared__ float red[17];
    __shared__ float wprod[17];

    int b = blockIdx.x, t = threadIdx.x;
    int lane = t & 31, wid = t >> 5;
    const float* ifcb = g_ifc[b];

    // ---- early loads: memory row + precedence (latency hidden by sort) ----
    float4 mreg[8];
    const float4* mrp = (const float4*)(mem_in + ((size_t)(b * NN + t)) * WD);
    #pragma unroll
    for (int q = 0; q < 8; q++) mreg[q] = mrp[q];
    float prec_v = prec_in[b * NN + t];

    // usage update (retention psi)
    float psi = 1.f;
    #pragma unroll
    for (int r = 0; r < RR; r++) {
        float fr = ifcb[229 + r];
        psi *= (1.f - fr * rw_in[((size_t)(b * RR + r)) * NN + t]);
    }
    float u = usage_in[b * NN + t], wp = wwp_in[b * NN + t];
    float un = (u + wp - u * wp) * psi;
    o_us[b * NN + t] = un;
    if (t < WD) {
        wk_s[t] = ifcb[132 + t];
        er_s[t] = ifcb[165 + t];
        wv_s[t] = ifcb[197 + t];
    }

    // ---- bitonic sort ascending (key + original index) ----
    // phase A: k = 2..32 entirely intra-warp, register resident
    {
        float a = un;
        int ia = t;
        #pragma unroll
        for (int k = 2; k <= 32; k <<= 1) {
            #pragma unroll
            for (int j = k >> 1; j >= 1; j >>= 1) {
                float pk = __shfl_xor_sync(0xffffffffu, a, j);
                int   pi = __shfl_xor_sync(0xffffffffu, ia, j);
                bool up = ((t & k) == 0);
                bool lower = ((t & j) == 0);
                bool keepmin = (lower == up);
                bool take = keepmin ? (pk < a) : (pk > a);
                if (take) { a = pk; ia = pi; }
            }
        }
        sk[t] = a; si[t] = ia;
    }
    __syncthreads();

    // phase B: k = 64..512 ; shared stages for j>=32, warp tail for j<=16
    for (int k = 64; k <= NN; k <<= 1) {
        for (int j = k >> 1; j >= 32; j >>= 1) {
            int ixj = t ^ j;
            if (ixj > t) {
                float a = sk[t], c = sk[ixj];
                bool up = ((t & k) == 0);
                if (up ? (a > c) : (a < c)) {
                    sk[t] = c; sk[ixj] = a;
                    int tmp = si[t]; si[t] = si[ixj]; si[ixj] = tmp;
                }
            }
            __syncthreads();
        }
        {
            float a = sk[t]; int ia = si[t];
            bool up = ((t & k) == 0);
            #pragma unroll
            for (int j = 16; j >= 1; j >>= 1) {
                float pk = __shfl_xor_sync(0xffffffffu, a, j);
                int   pi = __shfl_xor_sync(0xffffffffu, ia, j);
                bool lower = ((t & j) == 0);
                bool keepmin = (lower == up);
                bool take = keepmin ? (pk < a) : (pk > a);
                if (take) { a = pk; ia = pi; }
            }
            sk[t] = a; si[t] = ia;
        }
        __syncthreads();
    }

    // ---- exclusive cumprod of sorted usage via warp scan ----
    float key = sk[t];
    float xs = key;
    #pragma unroll
    for (int o = 1; o < 32; o <<= 1) {
        float y = __shfl_up_sync(0xffffffffu, xs, o);
        if (lane >= o) xs *= y;
    }
    if (lane == 31) wprod[wid] = xs;
    __syncthreads();
    if (t < 32) {
        float p = (t < 16) ? wprod[t] : 1.f;
        #pragma unroll
        for (int o = 1; o < 16; o <<= 1) {
            float y = __shfl_up_sync(0xffffffffu, p, o);
            if (lane >= o) p *= y;
        }
        if (t < 16) wprod[t] = p;
    }
    __syncthreads();
    float pre = (wid == 0) ? 1.f : wprod[wid - 1];
    float exclw = __shfl_up_sync(0xffffffffu, xs, 1);
    float excl = (lane == 0) ? pre : (exclw * pre);
    alloc_s[si[t]] = (1.f - key) * excl;   // scatter (permutation)

    // write content addressing on OLD memory (row already in registers)
    float kn2 = 0.f;
    #pragma unroll
    for (int w = 0; w < WD; w++) kn2 += wk_s[w] * wk_s[w];
    float knorm = sqrtf(kn2);

    const float4* wk4 = (const float4*)wk_s;
    float dot = 0.f, n2 = 0.f;
    #pragma unroll
    for (int q = 0; q < 8; q++) {
        float4 m = mreg[q], k4 = wk4[q];
        dot += m.x * k4.x + m.y * k4.y + m.z * k4.z + m.w * k4.w;
        n2  += m.x * m.x + m.y * m.y + m.z * m.z + m.w * m.w;
    }
    float wstr = ifcb[164];
    float s = wstr * dot / (sqrtf(n2) * knorm + EPSV);
    float mx = blockRedMax(s, red);          // syncthreads inside also fences alloc_s
    float e = expf(s - mx);
    float sum = blockRedSum(e, red);
    float wc = e / sum;

    float ag = ifcb[233], wg = ifcb[234];
    float av = alloc_s[t];
    float wwv = wg * (ag * av + (1.f - ag) * wc);
    o_ww[b * NN + t] = wwv;
    float sww = blockRedSum(wwv, red);
    o_prec[b * NN + t] = (1.f - sww) * prec_v + wwv;

    // fused memory write + row norm (this thread owns row t, data in mreg)
    const float4* er4 = (const float4*)er_s;
    const float4* wv4 = (const float4*)wv_s;
    float4* mo = (float4*)(o_mem + ((size_t)(b * NN + t)) * WD);
    float nrm2 = 0.f;
    #pragma unroll
    for (int q = 0; q < 8; q++) {
        float4 m = mreg[q], ee = er4[q], vv = wv4[q], o;
        o.x = m.x * (1.f - wwv * ee.x) + wwv * vv.x;
        o.y = m.y * (1.f - wwv * ee.y) + wwv * vv.y;
        o.z = m.z * (1.f - wwv * ee.z) + wwv * vv.z;
        o.w = m.w * (1.f - wwv * ee.w) + wwv * vv.w;
        mo[q] = o;
        nrm2 += o.x * o.x + o.y * o.y + o.z * o.z + o.w * o.w;
    }
    g_mnorm[b * NN + t] = sqrtf(nrm2);
}

// -------------------------------------------- K4: link update + fused fw / bw
// 2-buffer pipeline (R12 configuration: 80 regs, no spill under (256,3)).
__global__ void __launch_bounds__(256, 3) k_link(
    const float* __restrict__ link_in, const float* __restrict__ prec_in,
    const float* __restrict__ rw_in, const float* __restrict__ ww,
    float* __restrict__ o_link)
{
    __shared__ float4 rw4_s[NN];       // 8 KB
    __shared__ float  ww_s[NN];        // 2 KB
    __shared__ float  fw_s[RR][68];    // ~1 KB (padded)
    __shared__ float  bw_s[RR][NN];    // 8 KB

    int b = blockIdx.y, strip = blockIdx.x;   // strip 0..7, 64 rows each
    int t = threadIdx.x;
    int grp = t >> 7;                          // 0..1
    int tig = t & 127;
    int lane = t & 31;

    for (int i = t; i < NN; i += 256) {
        float4 v;
        v.x = rw_in[((size_t)(b * RR + 0)) * NN + i];
        v.y = rw_in[((size_t)(b * RR + 1)) * NN + i];
        v.z = rw_in[((size_t)(b * RR + 2)) * NN + i];
        v.w = rw_in[((size_t)(b * RR + 3)) * NN + i];
        rw4_s[i] = v;
        ww_s[i] = ww[b * NN + i];
    }
    for (int i = t; i < RR * 68; i += 256) (&fw_s[0][0])[i] = 0.f;
    for (int i = t; i < RR * NN; i += 256) (&bw_s[0][0])[i] = 0.f;
    __syncthreads();

    int m0 = tig * 4;
    float4 prec_own = *(const float4*)(prec_in + (size_t)b * NN + m0);
    float4 rw_own0 = rw4_s[m0 + 0];
    float4 rw_own1 = rw4_s[m0 + 1];
    float4 rw_own2 = rw4_s[m0 + 2];
    float4 rw_own3 = rw4_s[m0 + 3];
    float ww0 = ww_s[m0 + 0], ww1 = ww_s[m0 + 1];
    float ww2 = ww_s[m0 + 2], ww3 = ww_s[m0 + 3];

    int row0 = strip * 64 + grp * 32;
    const float* Lp = link_in + ((size_t)b * NN + row0) * NN + m0;
    float* Op = o_link + ((size_t)b * NN + row0) * NN + m0;

    float bacc[16];
    #pragma unroll
    for (int k = 0; k < 16; k++) bacc[k] = 0.f;

    // 16 chunks of 2 rows, with next-chunk prefetch (2-buffer)
    float4 A0 = __ldcs((const float4*)(Lp + 0 * NN));
    float4 A1 = __ldcs((const float4*)(Lp + 1 * NN));

    for (int c = 0; c < 16; c++) {
        float4 B0, B1;
        if (c < 15) {
            B0 = __ldcs((const float4*)(Lp + (size_t)(2 * c + 2) * NN));
            B1 = __ldcs((const float4*)(Lp + (size_t)(2 * c + 3) * NN));
        }

        float vals[8];
        #pragma unroll
        for (int j = 0; j < 2; j++) {
            float4 L4 = (j == 0) ? A0 : A1;
            int n = row0 + 2 * c + j;
            float wwn = ww_s[n];
            float4 rwn = rw4_s[n];
            float cn = 1.f - wwn;
            float l0 = fmaf(cn - ww0, L4.x, wwn * prec_own.x);
            float l1 = fmaf(cn - ww1, L4.y, wwn * prec_own.y);
            float l2 = fmaf(cn - ww2, L4.z, wwn * prec_own.z);
            float l3 = fmaf(cn - ww3, L4.w, wwn * prec_own.w);
            l0 = (n == m0 + 0) ? 0.f : l0;
            l1 = (n == m0 + 1) ? 0.f : l1;
            l2 = (n == m0 + 2) ? 0.f : l2;
            l3 = (n == m0 + 3) ? 0.f : l3;
            __stcs((float4*)(Op + (size_t)(2 * c + j) * NN), make_float4(l0, l1, l2, l3));

            vals[j * 4 + 0] = l0 * rw_own0.x + l1 * rw_own1.x + l2 * rw_own2.x + l3 * rw_own3.x;
            vals[j * 4 + 1] = l0 * rw_own0.y + l1 * rw_own1.y + l2 * rw_own2.y + l3 * rw_own3.y;
            vals[j * 4 + 2] = l0 * rw_own0.z + l1 * rw_own1.z + l2 * rw_own2.z + l3 * rw_own3.z;
            vals[j * 4 + 3] = l0 * rw_own0.w + l1 * rw_own1.w + l2 * rw_own2.w + l3 * rw_own3.w;

            bacc[0]  = fmaf(l0, rwn.x, bacc[0]);  bacc[1]  = fmaf(l0, rwn.y, bacc[1]);
            bacc[2]  = fmaf(l0, rwn.z, bacc[2]);  bacc[3]  = fmaf(l0, rwn.w, bacc[3]);
            bacc[4]  = fmaf(l1, rwn.x, bacc[4]);  bacc[5]  = fmaf(l1, rwn.y, bacc[5]);
            bacc[6]  = fmaf(l1, rwn.z, bacc[6]);  bacc[7]  = fmaf(l1, rwn.w, bacc[7]);
            bacc[8]  = fmaf(l2, rwn.x, bacc[8]);  bacc[9]  = fmaf(l2, rwn.y, bacc[9]);
            bacc[10] = fmaf(l2, rwn.z, bacc[10]); bacc[11] = fmaf(l2, rwn.w, bacc[11]);
            bacc[12] = fmaf(l3, rwn.x, bacc[12]); bacc[13] = fmaf(l3, rwn.y, bacc[13]);
            bacc[14] = fmaf(l3, rwn.z, bacc[14]); bacc[15] = fmaf(l3, rwn.w, bacc[15]);
        }

        // joint reduction of 8 values (2 rows x 4 r) in 9 SHFL
        float red8 = multiRed8(vals, lane);
        if ((lane & 3) == 0) {
            int v = (((lane >> 4) & 1) << 2) | (((lane >> 3) & 1) << 1) | ((lane >> 2) & 1);
            int jrow = v >> 2;          // 0..1
            int rr = v & 3;             // 0..3
            atomicAdd(&fw_s[rr][grp * 32 + 2 * c + jrow], red8);
        }

        A0 = B0; A1 = B1;
    }

    // flush bw column partials (2 groups collide per address -> 2-way atomics, once)
    #pragma unroll
    for (int j = 0; j < 4; j++) {
        atomicAdd(&bw_s[0][m0 + j], bacc[j * 4 + 0]);
        atomicAdd(&bw_s[1][m0 + j], bacc[j * 4 + 1]);
        atomicAdd(&bw_s[2][m0 + j], bacc[j * 4 + 2]);
        atomicAdd(&bw_s[3][m0 + j], bacc[j * 4 + 3]);
    }
    __syncthreads();

    for (int i = t; i < RR * 64; i += 256) {
        int r = i >> 6, nl = i & 63;
        g_fw[((size_t)(b * RR + r)) * NN + strip * 64 + nl] = fw_s[r][nl];
    }
    for (int i = t; i < RR * NN; i += 256)
        g_bwp[((size_t)b * NSTRIP + strip) * (RR * NN) + i] = (&bw_s[0][0])[i];
}

// ---------------------- K5: read content softmax (joint 4-head), combine, rv
// bw/fw combine inputs load BEFORE the softmax barriers so their DRAM latency
// overlaps the reductions.
__global__ void __launch_bounds__(512) k_read(
    const float* __restrict__ o_mem, float* __restrict__ o_rw, float* __restrict__ o_rv)
{
    __shared__ float rk_s[RR][WD];
    __shared__ float rc_s[RR][NN];
    __shared__ float red4[RR][16];
    __shared__ float gmax[RR], gsum[RR];
    __shared__ float knorm_s[RR], rs_s[RR], modes_s[RR][3];
    __shared__ float rv_part[4][RR * WD];

    int b = blockIdx.x, t = threadIdx.x;
    int lane = t & 31, wid = t >> 5;
    const float* ifcb = g_ifc[b];
    if (t < 128) rk_s[t >> 5][t & 31] = ifcb[t];
    if (t >= 128 && t < 132) rs_s[t - 128] = ifcb[t];
    __syncthreads();
    if (t < RR) {
        float s2 = 0.f;
        #pragma unroll
        for (int w = 0; w < WD; w++) s2 += rk_s[t][w] * rk_s[t][w];
        knorm_s[t] = sqrtf(s2);
    }
    if (t >= 8 && t < 8 + RR) {
        int r = t - 8;
        float a = ifcb[235 + r * 3], c = ifcb[236 + r * 3], d = ifcb[237 + r * 3];
        float mx = fmaxf(a, fmaxf(c, d));
        float ea = expf(a - mx), ec = expf(c - mx), ed = expf(d - mx);
        float inv = 1.f / (ea + ec + ed);
        modes_s[r][0] = ea * inv; modes_s[r][1] = ec * inv; modes_s[r][2] = ed * inv;
    }
    __syncthreads();

    // this thread's updated-memory row in registers
    float4 mreg[8];
    const float4* mr = (const float4*)(o_mem + ((size_t)(b * NN + t)) * WD);
    #pragma unroll
    for (int q = 0; q < 8; q++) mreg[q] = mr[q];
    float nm = g_mnorm[b * NN + t];

    // all 4 head scores for this row
    float sval[RR];
    #pragma unroll
    for (int r = 0; r < RR; r++) {
        const float4* rk4 = (const float4*)rk_s[r];
        float dot = 0.f;
        #pragma unroll
        for (int q = 0; q < 8; q++) {
            float4 k4 = rk4[q];
            dot += mreg[q].x * k4.x + mreg[q].y * k4.y + mreg[q].z * k4.z + mreg[q].w * k4.w;
        }
        sval[r] = rs_s[r] * dot / (nm * knorm_s[r] + EPSV);
    }

    // EARLY-ISSUE combine inputs: 36 independent loads overlap the barriers below
    float bwv[RR], fwv[RR];
    #pragma unroll
    for (int r = 0; r < RR; r++) {
        float acc = 0.f;
        #pragma unroll
        for (int s = 0; s < NSTRIP; s++)
            acc += g_bwp[((size_t)b * NSTRIP + s) * (RR * NN) + r * NN + t];
        bwv[r] = acc;
        fwv[r] = g_fw[((size_t)(b * RR + r)) * NN + t];
    }

    // joint block max for 4 heads (2 barriers)
    #pragma unroll
    for (int r = 0; r < RR; r++) {
        float v = sval[r];
        #pragma unroll
        for (int o = 16; o; o >>= 1) v = fmaxf(v, __shfl_xor_sync(0xffffffffu, v, o));
        if (lane == 0) red4[r][wid] = v;
    }
    __syncthreads();
    if (wid < RR) {
        float x = (lane < 16) ? red4[wid][lane] : -INFINITY;
        #pragma unroll
        for (int o = 16; o; o >>= 1) x = fmaxf(x, __shfl_xor_sync(0xffffffffu, x, o));
        if (lane == 0) gmax[wid] = x;
    }
    __syncthreads();

    // joint block sum for 4 heads (2 barriers)
    float ex[RR];
    #pragma unroll
    for (int r = 0; r < RR; r++) {
        ex[r] = expf(sval[r] - gmax[r]);
        float v = ex[r];
        #pragma unroll
        for (int o = 16; o; o >>= 1) v += __shfl_xor_sync(0xffffffffu, v, o);
        if (lane == 0) red4[r][wid] = v;
    }
    __syncthreads();
    if (wid < RR) {
        float x = (lane < 16) ? red4[wid][lane] : 0.f;
        #pragma unroll
        for (int o = 16; o; o >>= 1) x += __shfl_xor_sync(0xffffffffu, x, o);
        if (lane == 0) gsum[wid] = x;
    }
    __syncthreads();

    // combine modes: rw_new = m0*bw + m1*rc + m2*fw
    #pragma unroll
    for (int r = 0; r < RR; r++) {
        float rc = ex[r] / gsum[r];
        float val = modes_s[r][0] * bwv[r] + modes_s[r][1] * rc + modes_s[r][2] * fwv[r];
        o_rw[((size_t)(b * RR + r)) * NN + t] = val;
        rc_s[r][t] = val;
    }
    __syncthreads();

    // read vectors: rv[r][w] = sum_n rw[r][n] * mem[n][w]  (512 threads, 4 n-chunks)
    {
        int chunk = t >> 7;           // 0..3
        int p = t & 127;              // (r,w) pair
        int r = p >> 5, w = p & 31;
        float acc = 0.f;
        const float* mb = o_mem + (size_t)b * NN * WD;
        int n0 = chunk * 128;
        #pragma unroll 4
        for (int n = n0; n < n0 + 128; n++)
            acc = fmaf(rc_s[r][n], mb[(size_t)n * WD + w], acc);
        rv_part[chunk][p] = acc;
    }
    __syncthreads();
    if (t < RR * WD)
        o_rv[(size_t)b * RR * WD + t] =
            rv_part[0][t] + rv_part[1][t] + rv_part[2][t] + rv_part[3][t];
}

// ------------------------------------------------------------------ launcher
extern "C" void kernel_launch(void* const* d_in, const int* in_sizes, int n_in,
                              void* d_out, int out_size)
{
    (void)in_sizes; (void)n_in; (void)out_size;
    const float* xi       = (const float*)d_in[0];
    const float* mem_in   = (const float*)d_in[1];
    const float* link_in  = (const float*)d_in[2];
    const float* prec_in  = (const float*)d_in[3];
    const float* rw_in    = (const float*)d_in[4];
    const float* wwp_in   = (const float*)d_in[5];
    const float* usage_in = (const float*)d_in[6];

    HeadPtrs P;
    for (int h = 0; h < 10; h++) {
        P.W[h]  = (const float*)d_in[7 + 2 * h];
        P.Bv[h] = (const float*)d_in[8 + 2 * h];
    }

    float* out    = (float*)d_out;
    float* o_rv   = out + O_RV;
    float* o_mem  = out + O_MEM;
    float* o_link = out + O_LINK;
    float* o_prec = out + O_PREC;
    float* o_rw   = out + O_RW;
    float* o_ww   = out + O_WW;
    float* o_us   = out + O_US;

    k_interface<<<dim3(31, 16), 256>>>(xi, P);
    k_batch<<<BB, 512>>>(mem_in, prec_in, rw_in, wwp_in, usage_in, o_ww, o_prec, o_us, o_mem);
    k_link<<<dim3(NSTRIP, BB), 256>>>(link_in, prec_in, rw_in, o_ww, o_link);
    k_read<<<BB, 512>>>(o_mem, o_rw, o_rv);
}